// round 14
// baseline (speedup 1.0000x reference)
#include <cuda_runtime.h>
#include <cuda_bf16.h>
#include <cstdint>
#include <math.h>

#define NBLK 148
#define NTEAM (NBLK * 2)

// ================= scratch (device globals: no allocation allowed) =================
__device__ __align__(16) float g_zT [2000 * 64];
__device__ __align__(16) float g_b3T[100 * 64];
__device__ __align__(16) float g_b4T[200 * 64];
__device__ __align__(16) float g_p1[3 * 200 * 64];
__device__ __align__(16) float g_p2[2 * 200 * 64];
// h B-fragments: [side][wn][lane][8 x uint4] (words 0..15 = hi, 16..31 = lo)
__device__ __align__(16) uint4 g_frag[2][4][32][8];
__device__ int g_barc[8];

// ================= helpers =================
__device__ __forceinline__ uint32_t smem_u32(const void* p) {
    uint32_t a;
    asm("{ .reg .u64 t; cvta.to.shared.u64 t, %1; cvt.u32.u64 %0, t; }" : "=r"(a) : "l"(p));
    return a;
}
__device__ __forceinline__ void ldsm_x4(uint32_t* r, uint32_t addr) {
    asm volatile("ldmatrix.sync.aligned.m8n8.x4.shared.b16 {%0,%1,%2,%3}, [%4];"
        : "=r"(r[0]), "=r"(r[1]), "=r"(r[2]), "=r"(r[3]) : "r"(addr));
}
__device__ __forceinline__ void ldsm_x2(uint32_t* r, uint32_t addr) {
    asm volatile("ldmatrix.sync.aligned.m8n8.x2.shared.b16 {%0,%1}, [%2];"
        : "=r"(r[0]), "=r"(r[1]) : "r"(addr));
}
__device__ __forceinline__ void mma_bf16(float* d, const uint32_t* a, const uint32_t* b) {
    asm volatile("mma.sync.aligned.m16n8k16.row.col.f32.bf16.bf16.f32 "
        "{%0,%1,%2,%3}, {%4,%5,%6,%7}, {%8,%9}, {%0,%1,%2,%3};"
        : "+f"(d[0]), "+f"(d[1]), "+f"(d[2]), "+f"(d[3])
        : "r"(a[0]), "r"(a[1]), "r"(a[2]), "r"(a[3]), "r"(b[0]), "r"(b[1]));
}
__device__ __forceinline__ uint32_t prmt_hi(float a, float b) {
    uint32_t r;
    asm("prmt.b32 %0, %1, %2, 0x7632;"
        : "=r"(r) : "r"(__float_as_uint(a)), "r"(__float_as_uint(b)));
    return r;
}
__device__ __forceinline__ uint32_t pack_lo_resid(float a, float b) {
    float la = a - __uint_as_float(__float_as_uint(a) & 0xffff0000u);
    float lb = b - __uint_as_float(__float_as_uint(b) & 0xffff0000u);
    uint32_t r;
    asm("cvt.rn.bf16x2.f32 %0, %1, %2;" : "=r"(r) : "f"(lb), "f"(la));
    return r;
}

// grid-wide barrier: arrive with release, spin with acquire (thread 0 only)
__device__ __forceinline__ void gbar(int ph) {
    __syncthreads();
    if (threadIdx.x == 0) {
        __threadfence();
        atomicAdd(&g_barc[ph], 1);
        int v;
        do {
            asm volatile("ld.acquire.gpu.b32 %0, [%1];" : "=r"(v) : "l"(&g_barc[ph]) : "memory");
        } while (v < NBLK);
    }
    __syncthreads();
}

// ================= smem layout =================
// layers: wt[team] 9216 each @0, b2s float[2][3][16] @18432 (384)
// phase0 overlay: mus @0 (1024), h1 @1024 (16640), hsH @17664 (9216), hsL @26880 (9216)
#define SM_BYTES 36608

// ================= fused hyper-FC layer (one phase) =================
// Team (128 thr) owns task = (channel, K-split); static stride NTEAM.
// Per 16-row tile: D[j,b] = Wrows @ h^T (3-term bf16 split, fp32 acc);
//   acc[b] += (D[j,b] + b2[j]) * x'[j,b]   (x'[ni] = 1 folds the layer bias).
// x read from xsrc; if np>1 sums np partial arrays (stride pstride), opt tanh.
__device__ __noinline__ void run_layer(
    char* sm, const uint4* hfrag,
    const float* __restrict__ W2, const float* __restrict__ b2,
    const float* __restrict__ xsrc, int np, int pstride, int xtanh,
    float* __restrict__ part_out, float* __restrict__ outT,
    float* __restrict__ outR, int ostride, int otanh,
    int ni, int no, long off, int nsplit)
{
    const int tid = threadIdx.x, lane = tid & 31, wid = tid >> 5;
    const int team = wid >> 2, wn = wid & 3, tt = tid & 127;
    char* wt = sm + team * 9216;                       // 2 stages x {hi 2304, lo 2304}
    float* b2s = (float*)(sm + 18432) + team * 48;     // [3 slots][16]
    const uint32_t wtb = smem_u32(wt);
    const int barid = 1 + team;
    const int sr = tt >> 3, sq = tt & 7;

    // ---- B fragments: 8 coalesced LDG.128 ----
    uint32_t bh[2][4][2], bl[2][4][2];
    {
        const uint4* fp = hfrag + (wn * 32 + lane) * 8;
        uint32_t w_[32];
#pragma unroll
        for (int j = 0; j < 8; j++) {
            uint4 v = fp[j];
            w_[4*j] = v.x; w_[4*j+1] = v.y; w_[4*j+2] = v.z; w_[4*j+3] = v.w;
        }
#pragma unroll
        for (int nt = 0; nt < 2; nt++)
#pragma unroll
        for (int ks = 0; ks < 4; ks++)
#pragma unroll
        for (int r = 0; r < 2; r++) {
            bh[nt][ks][r] = w_[nt * 8 + ks * 2 + r];
            bl[nt][ks][r] = w_[16 + nt * 8 + ks * 2 + r];
        }
    }

    const int K1 = ni + 1;
    const int ilen = (K1 + nsplit - 1) / nsplit;
    const int ntasks = no * nsplit;

    for (int task = blockIdx.x * 2 + team; task < ntasks; task += NTEAM) {
        const int cc = task / nsplit, split = task % nsplit;
        const int ibeg = split * ilen;
        const int iend = min(ibeg + ilen, K1);
        const int ntiles = (iend - ibeg + 15) >> 4;
        const long wbase = off + (long)cc * ni;
        const long brow  = off + (long)ni * no + cc;

        float4 pwa[3], pwb[3]; float pb2[3];
        auto ldg_tile = [&](int t) {
            int s = t % 3;
            int gi = ibeg + t * 16 + sr;
            bool valid = gi < iend;
            long row = (gi < ni) ? (wbase + gi) : brow;
            const float4 f40 = make_float4(0.f, 0.f, 0.f, 0.f);
            pwa[s] = valid ? *(const float4*)(W2 + row * 64 + sq * 8)     : f40;
            pwb[s] = valid ? *(const float4*)(W2 + row * 64 + sq * 8 + 4) : f40;
            pb2[s] = (valid && sq == 0) ? b2[row] : 0.f;
        };
        auto sts_tile = [&](int t) {
            int s = t % 3, sbuf = t & 1;
            char* ph = wt + sbuf * 4608 + sr * 144 + sq * 16;
            uint4 H, L;
            H.x = prmt_hi(pwa[s].x, pwa[s].y); H.y = prmt_hi(pwa[s].z, pwa[s].w);
            H.z = prmt_hi(pwb[s].x, pwb[s].y); H.w = prmt_hi(pwb[s].z, pwb[s].w);
            L.x = pack_lo_resid(pwa[s].x, pwa[s].y); L.y = pack_lo_resid(pwa[s].z, pwa[s].w);
            L.z = pack_lo_resid(pwb[s].x, pwb[s].y); L.w = pack_lo_resid(pwb[s].z, pwb[s].w);
            *(uint4*)ph = H;
            *(uint4*)(ph + 2304) = L;
            if (sq == 0) b2s[sbuf * 16 + sr] = pb2[s];
        };

        ldg_tile(0);
        if (ntiles > 1) ldg_tile(1);
        if (ntiles > 2) ldg_tile(2);
        asm volatile("bar.sync %0, 128;" :: "r"(barid) : "memory");  // prev task done with smem
        sts_tile(0);

        float acc[4] = {0.f, 0.f, 0.f, 0.f};
        const float2 z2 = make_float2(0.f, 0.f);

        for (int mt = 0; mt < ntiles; ++mt) {
            if (mt + 3 < ntiles) ldg_tile(mt + 3);
            asm volatile("bar.sync %0, 128;" :: "r"(barid) : "memory");

            // ---- x loads (inline partial-sum + opt tanh) ----
            const int g0 = ibeg + mt * 16 + (lane >> 2);
            const int g1 = g0 + 8;
            const bool v0 = g0 < iend, v1 = g1 < iend;
            float2 x0[2], x1[2];
#pragma unroll
            for (int nt = 0; nt < 2; nt++) {
                int col = wn * 16 + nt * 8 + (lane & 3) * 2;
#pragma unroll
                for (int half = 0; half < 2; half++) {
                    int g = half ? g1 : g0;
                    bool v = half ? v1 : v0;
                    float2 xv = z2;
                    if (v) {
                        if (g == ni) xv = make_float2(1.f, 1.f);
                        else {
                            const float* p = xsrc + (long)g * 64 + col;
                            xv = *(const float2*)p;
                            if (np > 1) {
                                float2 a = *(const float2*)(p + pstride);
                                xv.x += a.x; xv.y += a.y;
                                if (np > 2) {
                                    float2 b = *(const float2*)(p + 2 * pstride);
                                    xv.x += b.x; xv.y += b.y;
                                }
                            }
                            if (xtanh) { xv.x = tanhf(xv.x); xv.y = tanhf(xv.y); }
                        }
                    }
                    if (half) x1[nt] = xv; else x0[nt] = xv;
                }
            }

            // ---- A fragments via ldmatrix ----
            const int buf = mt & 1;
            uint32_t aH[4][4], aL[4][4];
            {
                int lrow = (lane & 7) + ((lane >> 3) & 1) * 8;
                int kh = lane >> 4;
                uint32_t base = wtb + buf * 4608 + (uint32_t)(lrow * 144 + kh * 16);
#pragma unroll
                for (int ks = 0; ks < 4; ks++) {
                    ldsm_x4(aH[ks], base + ks * 32);
                    ldsm_x4(aL[ks], base + 2304 + ks * 32);
                }
            }

            // ---- MMA (3-term split) ----
            float d[2][4] = {{0.f,0.f,0.f,0.f},{0.f,0.f,0.f,0.f}};
#pragma unroll
            for (int ks = 0; ks < 4; ks++) {
#pragma unroll
                for (int nt = 0; nt < 2; nt++) {
                    mma_bf16(d[nt], aH[ks], bh[nt][ks]);
                    mma_bf16(d[nt], aH[ks], bl[nt][ks]);
                    mma_bf16(d[nt], aL[ks], bh[nt][ks]);
                }
            }

            // ---- fold bias + x ----
            const float bb0 = b2s[buf * 16 + (lane >> 2)];
            const float bb1 = b2s[buf * 16 + (lane >> 2) + 8];
#pragma unroll
            for (int nt = 0; nt < 2; nt++) {
                acc[nt * 2 + 0] += (d[nt][0] + bb0) * x0[nt].x + (d[nt][2] + bb1) * x1[nt].x;
                acc[nt * 2 + 1] += (d[nt][1] + bb0) * x0[nt].y + (d[nt][3] + bb1) * x1[nt].y;
            }

            if (mt + 1 < ntiles) sts_tile(mt + 1);
        }

        // ---- reduce over j-groups (lane bits 2..4) and write ----
#pragma unroll
        for (int e = 0; e < 4; e++) {
            acc[e] += __shfl_xor_sync(0xffffffffu, acc[e], 4);
            acc[e] += __shfl_xor_sync(0xffffffffu, acc[e], 8);
            acc[e] += __shfl_xor_sync(0xffffffffu, acc[e], 16);
        }
        if (lane < 4) {
#pragma unroll
            for (int nt = 0; nt < 2; nt++)
#pragma unroll
            for (int e2 = 0; e2 < 2; e2++) {
                int col = wn * 16 + nt * 8 + lane * 2 + e2;
                float v = acc[nt * 2 + e2];
                if (part_out) {
                    part_out[(long)split * (no * 64) + (long)cc * 64 + col] = v;
                } else {
                    if (otanh) v = tanhf(v);
                    if (outT) outT[(long)cc * 64 + col] = v;
                    if (outR) outR[(long)col * ostride + cc] = v;
                }
            }
        }
    }
}

// ================= the persistent kernel =================
__global__ void __launch_bounds__(256, 1) persist(
    const float* __restrict__ z, const float* __restrict__ mu,
    const float* __restrict__ enW0, const float* __restrict__ enb0,
    const float* __restrict__ enW1, const float* __restrict__ enb1,
    const float* __restrict__ enW2, const float* __restrict__ enb2,
    const float* __restrict__ deW0, const float* __restrict__ deb0,
    const float* __restrict__ deW1, const float* __restrict__ deb1,
    const float* __restrict__ deW2, const float* __restrict__ deb2,
    float* __restrict__ out)
{
    __shared__ __align__(16) char sm[SM_BYTES];
    const int tid = threadIdx.x;

    // ======== phase 0: hyper (blocks 0,1) + z transpose (all blocks) ========
    if (blockIdx.x < 2) {
        const int side = blockIdx.x;
        const float* W0; const float* b0; const float* W1; const float* b1;
        if (side == 0) { W0 = enW0; b0 = enb0; W1 = enW1; b1 = enb1; }
        else           { W0 = deW0; b0 = deb0; W1 = deW1; b1 = deb1; }
        float* mus = (float*)sm;                       // 256 floats
        float (*h1)[65] = (float(*)[65])(sm + 1024);   // 64 x 65
        __nv_bfloat16* hsH = (__nv_bfloat16*)(sm + 17664);
        __nv_bfloat16* hsL = (__nv_bfloat16*)(sm + 26880);

        mus[tid] = mu[tid];
        __syncthreads();
        for (int idx = tid; idx < 4096; idx += 256) {
            int b = idx >> 6, o = idx & 63;
            float s = b0[o];
#pragma unroll
            for (int j = 0; j < 4; j++) s += mus[b * 4 + j] * W0[o * 4 + j];
            h1[b][o] = tanhf(s);
        }
        __syncthreads();
        for (int idx = tid; idx < 4096; idx += 256) {
            int b = idx >> 6, o = idx & 63;
            float s = b1[o];
#pragma unroll
            for (int k = 0; k < 64; k++) s += h1[b][k] * W1[o * 64 + k];
            float f = tanhf(s);
            __nv_bfloat16 hi = __float2bfloat16_rn(f);
            __nv_bfloat16 lo = __float2bfloat16_rn(f - __bfloat162float(hi));
            hsH[b * 72 + o] = hi;
            hsL[b * 72 + o] = lo;
        }
        __syncthreads();
        int wid = tid >> 5, lane = tid & 31;
        if (wid < 4) {
            const int wn = wid;
            const uint32_t smbH = smem_u32(hsH), smbL = smem_u32(hsL);
            uint32_t w_[32];
            int l2 = lane & 15, rr = l2 & 7, rs = l2 >> 3;
#pragma unroll
            for (int nt = 0; nt < 2; nt++) {
                int bb = wn * 16 + nt * 8 + rr;
#pragma unroll
                for (int ks = 0; ks < 4; ks++) {
                    uint32_t o_ = (uint32_t)(bb * 144 + ks * 32 + rs * 16);
                    uint32_t th[2], tl[2];
                    ldsm_x2(th, smbH + o_);
                    ldsm_x2(tl, smbL + o_);
                    w_[nt * 8 + ks * 2 + 0] = th[0];
                    w_[nt * 8 + ks * 2 + 1] = th[1];
                    w_[16 + nt * 8 + ks * 2 + 0] = tl[0];
                    w_[16 + nt * 8 + ks * 2 + 1] = tl[1];
                }
            }
#pragma unroll
            for (int j = 0; j < 8; j++)
                g_frag[side][wn][lane][j] = make_uint4(w_[4*j], w_[4*j+1], w_[4*j+2], w_[4*j+3]);
        }
    }
    // z transpose (all blocks share)
    for (int idx = blockIdx.x * 256 + tid; idx < 2000 * 64; idx += NBLK * 256) {
        int i = idx >> 6, b = idx & 63;
        g_zT[idx] = z[b * 2000 + i];
    }
    gbar(0);

    const uint4* fragEn = &g_frag[0][0][0][0];
    const uint4* fragDe = &g_frag[1][0][0][0];

    // ======== phase 1: encoder L0  2000 -> 200, linear, 3 K-splits -> p1 ========
    run_layer(sm, fragEn, enW2, enb2, g_zT, 1, 0, 0,
              g_p1, nullptr, nullptr, 0, 0, 2000, 200, 0L, 3);
    gbar(1);
    // ======== phase 2: encoder L1  200 -> 100 (x = sum3 p1), 2 splits -> p2 ========
    run_layer(sm, fragEn, enW2, enb2, g_p1, 3, 12800, 0,
              g_p2, nullptr, nullptr, 0, 0, 200, 100, 400200L, 2);
    gbar(2);
    // ======== phase 3: encoder L2  100 -> 10 (x = tanh(sum2 p2)), 2 splits -> p1 ========
    run_layer(sm, fragEn, enW2, enb2, g_p2, 2, 6400, 1,
              g_p1, nullptr, nullptr, 0, 0, 100, 10, 420300L, 2);
    gbar(3);
    // ======== phase 4: decoder L0  10 -> 100 (x = sum2 p1), direct b3T; latent tail ========
    if (blockIdx.x == NBLK - 1) {
        for (int i = tid; i < 640; i += 256) {
            int cc = i >> 6, col = i & 63;
            out[128000 + col * 10 + cc] = g_p1[i] + g_p1[640 + i];
        }
    }
    run_layer(sm, fragDe, deW2, deb2, g_p1, 2, 640, 0,
              nullptr, g_b3T, nullptr, 0, 0, 10, 100, 0L, 1);
    gbar(4);
    // ======== phase 5: decoder L1  100 -> 200, tanh at write -> b4T ========
    run_layer(sm, fragDe, deW2, deb2, g_b3T, 1, 0, 0,
              nullptr, g_b4T, nullptr, 0, 1, 100, 200, 1100L, 1);
    gbar(5);
    // ======== phase 6: decoder L2  200 -> 2000, direct row-major to d_out ========
    run_layer(sm, fragDe, deW2, deb2, g_b4T, 1, 0, 0,
              nullptr, nullptr, out, 2000, 0, 200, 2000, 21300L, 1);
}

extern "C" void kernel_launch(void* const* d_in, const int* in_sizes, int n_in,
                              void* d_out, int out_size)
{
    const float* z    = (const float*)d_in[0];
    const float* mu   = (const float*)d_in[1];
    const float* enW0 = (const float*)d_in[2];
    const float* enb0 = (const float*)d_in[3];
    const float* enW1 = (const float*)d_in[4];
    const float* enb1 = (const float*)d_in[5];
    const float* enW2 = (const float*)d_in[6];
    const float* enb2 = (const float*)d_in[7];
    const float* deW0 = (const float*)d_in[8];
    const float* deb0 = (const float*)d_in[9];
    const float* deW1 = (const float*)d_in[10];
    const float* deb1 = (const float*)d_in[11];
    const float* deW2 = (const float*)d_in[12];
    const float* deb2 = (const float*)d_in[13];
    float* out = (float*)d_out;

    void* barc;
    cudaGetSymbolAddress(&barc, g_barc);
    cudaMemsetAsync(barc, 0, 8 * sizeof(int));

    persist<<<NBLK, 256>>>(z, mu, enW0, enb0, enW1, enb1, enW2, enb2,
                           deW0, deb0, deW1, deb1, deW2, deb2, out);
}

// round 15
// speedup vs baseline: 1.0048x; 1.0048x over previous
#include <cuda_runtime.h>
#include <cuda_bf16.h>
#include <cstdint>
#include <math.h>

#define NBLK 148
#define NTEAM (NBLK * 2)

// ================= scratch (device globals: no allocation allowed) =================
__device__ __align__(16) float g_zT [2000 * 64];
__device__ __align__(16) float g_b3T[100 * 64];
__device__ __align__(16) float g_b4T[200 * 64];
__device__ __align__(16) float g_p1[3 * 200 * 64];
__device__ __align__(16) float g_p2[2 * 200 * 64];
// h B-fragments: [side][wn][lane][8 x uint4] (words 0..15 = hi, 16..31 = lo)
__device__ __align__(16) uint4 g_frag[2][4][32][8];
__device__ int g_barc[8];

// ================= helpers =================
__device__ __forceinline__ uint32_t smem_u32(const void* p) {
    uint32_t a;
    asm("{ .reg .u64 t; cvta.to.shared.u64 t, %1; cvt.u32.u64 %0, t; }" : "=r"(a) : "l"(p));
    return a;
}
__device__ __forceinline__ void ldsm_x4(uint32_t* r, uint32_t addr) {
    asm volatile("ldmatrix.sync.aligned.m8n8.x4.shared.b16 {%0,%1,%2,%3}, [%4];"
        : "=r"(r[0]), "=r"(r[1]), "=r"(r[2]), "=r"(r[3]) : "r"(addr));
}
__device__ __forceinline__ void ldsm_x2(uint32_t* r, uint32_t addr) {
    asm volatile("ldmatrix.sync.aligned.m8n8.x2.shared.b16 {%0,%1}, [%2];"
        : "=r"(r[0]), "=r"(r[1]) : "r"(addr));
}
__device__ __forceinline__ void mma_bf16(float* d, const uint32_t* a, const uint32_t* b) {
    asm volatile("mma.sync.aligned.m16n8k16.row.col.f32.bf16.bf16.f32 "
        "{%0,%1,%2,%3}, {%4,%5,%6,%7}, {%8,%9}, {%0,%1,%2,%3};"
        : "+f"(d[0]), "+f"(d[1]), "+f"(d[2]), "+f"(d[3])
        : "r"(a[0]), "r"(a[1]), "r"(a[2]), "r"(a[3]), "r"(b[0]), "r"(b[1]));
}
__device__ __forceinline__ uint32_t prmt_hi(float a, float b) {
    uint32_t r;
    asm("prmt.b32 %0, %1, %2, 0x7632;"
        : "=r"(r) : "r"(__float_as_uint(a)), "r"(__float_as_uint(b)));
    return r;
}
__device__ __forceinline__ uint32_t pack_lo_resid(float a, float b) {
    float la = a - __uint_as_float(__float_as_uint(a) & 0xffff0000u);
    float lb = b - __uint_as_float(__float_as_uint(b) & 0xffff0000u);
    uint32_t r;
    asm("cvt.rn.bf16x2.f32 %0, %1, %2;" : "=r"(r) : "f"(lb), "f"(la));
    return r;
}

// grid-wide barrier: arrive with release, spin with acquire (thread 0 only)
__device__ __forceinline__ void gbar(int ph) {
    __syncthreads();
    if (threadIdx.x == 0) {
        __threadfence();
        atomicAdd(&g_barc[ph], 1);
        int v;
        do {
            asm volatile("ld.acquire.gpu.b32 %0, [%1];" : "=r"(v) : "l"(&g_barc[ph]) : "memory");
        } while (v < NBLK);
    }
    __syncthreads();
}

// ================= smem layout =================
// layers: wt[team] 9216 each @0, b2s float[2][3][16] @18432 (384)
// phase0 overlay: mus @0 (1024), h1 @1024 (16640), hsH @17664 (9216), hsL @26880 (9216)
#define SM_BYTES 36608

// ================= fused hyper-FC layer (one phase) =================
// Team (128 thr) owns task = (channel, K-split); static stride NTEAM.
// Per 16-row tile: D[j,b] = Wrows @ h^T (3-term bf16 split, fp32 acc);
//   acc[b] += (D[j,b] + b2[j]) * x'[j,b]   (x'[ni] = 1 folds the layer bias).
// x read from xsrc; if np>1 sums np partial arrays (stride pstride), opt tanh.
__device__ __noinline__ void run_layer(
    char* sm, const uint4* hfrag,
    const float* __restrict__ W2, const float* __restrict__ b2,
    const float* __restrict__ xsrc, int np, int pstride, int xtanh,
    float* __restrict__ part_out, float* __restrict__ outT,
    float* __restrict__ outR, int ostride, int otanh,
    int ni, int no, long off, int nsplit)
{
    const int tid = threadIdx.x, lane = tid & 31, wid = tid >> 5;
    const int team = wid >> 2, wn = wid & 3, tt = tid & 127;
    char* wt = sm + team * 9216;                       // 2 stages x {hi 2304, lo 2304}
    float* b2s = (float*)(sm + 18432) + team * 48;     // [3 slots][16]
    const uint32_t wtb = smem_u32(wt);
    const int barid = 1 + team;
    const int sr = tt >> 3, sq = tt & 7;

    // ---- B fragments: 8 coalesced LDG.128 ----
    uint32_t bh[2][4][2], bl[2][4][2];
    {
        const uint4* fp = hfrag + (wn * 32 + lane) * 8;
        uint32_t w_[32];
#pragma unroll
        for (int j = 0; j < 8; j++) {
            uint4 v = fp[j];
            w_[4*j] = v.x; w_[4*j+1] = v.y; w_[4*j+2] = v.z; w_[4*j+3] = v.w;
        }
#pragma unroll
        for (int nt = 0; nt < 2; nt++)
#pragma unroll
        for (int ks = 0; ks < 4; ks++)
#pragma unroll
        for (int r = 0; r < 2; r++) {
            bh[nt][ks][r] = w_[nt * 8 + ks * 2 + r];
            bl[nt][ks][r] = w_[16 + nt * 8 + ks * 2 + r];
        }
    }

    const int K1 = ni + 1;
    const int ilen = (K1 + nsplit - 1) / nsplit;
    const int ntasks = no * nsplit;

    for (int task = blockIdx.x * 2 + team; task < ntasks; task += NTEAM) {
        const int cc = task / nsplit, split = task % nsplit;
        const int ibeg = split * ilen;
        const int iend = min(ibeg + ilen, K1);
        const int ntiles = (iend - ibeg + 15) >> 4;
        const long wbase = off + (long)cc * ni;
        const long brow  = off + (long)ni * no + cc;

        float4 pwa[3], pwb[3]; float pb2[3];
        auto ldg_tile = [&](int t) {
            int s = t % 3;
            int gi = ibeg + t * 16 + sr;
            bool valid = gi < iend;
            long row = (gi < ni) ? (wbase + gi) : brow;
            const float4 f40 = make_float4(0.f, 0.f, 0.f, 0.f);
            pwa[s] = valid ? *(const float4*)(W2 + row * 64 + sq * 8)     : f40;
            pwb[s] = valid ? *(const float4*)(W2 + row * 64 + sq * 8 + 4) : f40;
            pb2[s] = (valid && sq == 0) ? b2[row] : 0.f;
        };
        auto sts_tile = [&](int t) {
            int s = t % 3, sbuf = t & 1;
            char* ph = wt + sbuf * 4608 + sr * 144 + sq * 16;
            uint4 H, L;
            H.x = prmt_hi(pwa[s].x, pwa[s].y); H.y = prmt_hi(pwa[s].z, pwa[s].w);
            H.z = prmt_hi(pwb[s].x, pwb[s].y); H.w = prmt_hi(pwb[s].z, pwb[s].w);
            L.x = pack_lo_resid(pwa[s].x, pwa[s].y); L.y = pack_lo_resid(pwa[s].z, pwa[s].w);
            L.z = pack_lo_resid(pwb[s].x, pwb[s].y); L.w = pack_lo_resid(pwb[s].z, pwb[s].w);
            *(uint4*)ph = H;
            *(uint4*)(ph + 2304) = L;
            if (sq == 0) b2s[sbuf * 16 + sr] = pb2[s];
        };

        ldg_tile(0);
        if (ntiles > 1) ldg_tile(1);
        if (ntiles > 2) ldg_tile(2);
        asm volatile("bar.sync %0, 128;" :: "r"(barid) : "memory");  // prev task done with smem
        sts_tile(0);

        float acc[4] = {0.f, 0.f, 0.f, 0.f};
        const float2 z2 = make_float2(0.f, 0.f);

        for (int mt = 0; mt < ntiles; ++mt) {
            if (mt + 3 < ntiles) ldg_tile(mt + 3);
            asm volatile("bar.sync %0, 128;" :: "r"(barid) : "memory");

            // ---- x loads (inline partial-sum + opt tanh) ----
            const int g0 = ibeg + mt * 16 + (lane >> 2);
            const int g1 = g0 + 8;
            const bool v0 = g0 < iend, v1 = g1 < iend;
            float2 x0[2], x1[2];
#pragma unroll
            for (int nt = 0; nt < 2; nt++) {
                int col = wn * 16 + nt * 8 + (lane & 3) * 2;
#pragma unroll
                for (int half = 0; half < 2; half++) {
                    int g = half ? g1 : g0;
                    bool v = half ? v1 : v0;
                    float2 xv = z2;
                    if (v) {
                        if (g == ni) xv = make_float2(1.f, 1.f);
                        else {
                            const float* p = xsrc + (long)g * 64 + col;
                            xv = *(const float2*)p;
                            if (np > 1) {
                                float2 a = *(const float2*)(p + pstride);
                                xv.x += a.x; xv.y += a.y;
                                if (np > 2) {
                                    float2 b = *(const float2*)(p + 2 * pstride);
                                    xv.x += b.x; xv.y += b.y;
                                }
                            }
                            if (xtanh) { xv.x = tanhf(xv.x); xv.y = tanhf(xv.y); }
                        }
                    }
                    if (half) x1[nt] = xv; else x0[nt] = xv;
                }
            }

            // ---- A fragments via ldmatrix ----
            const int buf = mt & 1;
            uint32_t aH[4][4], aL[4][4];
            {
                int lrow = (lane & 7) + ((lane >> 3) & 1) * 8;
                int kh = lane >> 4;
                uint32_t base = wtb + buf * 4608 + (uint32_t)(lrow * 144 + kh * 16);
#pragma unroll
                for (int ks = 0; ks < 4; ks++) {
                    ldsm_x4(aH[ks], base + ks * 32);
                    ldsm_x4(aL[ks], base + 2304 + ks * 32);
                }
            }

            // ---- MMA (3-term split) ----
            float d[2][4] = {{0.f,0.f,0.f,0.f},{0.f,0.f,0.f,0.f}};
#pragma unroll
            for (int ks = 0; ks < 4; ks++) {
#pragma unroll
                for (int nt = 0; nt < 2; nt++) {
                    mma_bf16(d[nt], aH[ks], bh[nt][ks]);
                    mma_bf16(d[nt], aH[ks], bl[nt][ks]);
                    mma_bf16(d[nt], aL[ks], bh[nt][ks]);
                }
            }

            // ---- fold bias + x ----
            const float bb0 = b2s[buf * 16 + (lane >> 2)];
            const float bb1 = b2s[buf * 16 + (lane >> 2) + 8];
#pragma unroll
            for (int nt = 0; nt < 2; nt++) {
                acc[nt * 2 + 0] += (d[nt][0] + bb0) * x0[nt].x + (d[nt][2] + bb1) * x1[nt].x;
                acc[nt * 2 + 1] += (d[nt][1] + bb0) * x0[nt].y + (d[nt][3] + bb1) * x1[nt].y;
            }

            if (mt + 1 < ntiles) sts_tile(mt + 1);
        }

        // ---- reduce over j-groups (lane bits 2..4) and write ----
#pragma unroll
        for (int e = 0; e < 4; e++) {
            acc[e] += __shfl_xor_sync(0xffffffffu, acc[e], 4);
            acc[e] += __shfl_xor_sync(0xffffffffu, acc[e], 8);
            acc[e] += __shfl_xor_sync(0xffffffffu, acc[e], 16);
        }
        if (lane < 4) {
#pragma unroll
            for (int nt = 0; nt < 2; nt++)
#pragma unroll
            for (int e2 = 0; e2 < 2; e2++) {
                int col = wn * 16 + nt * 8 + lane * 2 + e2;
                float v = acc[nt * 2 + e2];
                if (part_out) {
                    part_out[(long)split * (no * 64) + (long)cc * 64 + col] = v;
                } else {
                    if (otanh) v = tanhf(v);
                    if (outT) outT[(long)cc * 64 + col] = v;
                    if (outR) outR[(long)col * ostride + cc] = v;
                }
            }
        }
    }
}

// ================= the persistent kernel =================
__global__ void __launch_bounds__(256, 1) persist(
    const float* __restrict__ z, const float* __restrict__ mu,
    const float* __restrict__ enW0, const float* __restrict__ enb0,
    const float* __restrict__ enW1, const float* __restrict__ enb1,
    const float* __restrict__ enW2, const float* __restrict__ enb2,
    const float* __restrict__ deW0, const float* __restrict__ deb0,
    const float* __restrict__ deW1, const float* __restrict__ deb1,
    const float* __restrict__ deW2, const float* __restrict__ deb2,
    float* __restrict__ out)
{
    __shared__ __align__(16) char sm[SM_BYTES];
    const int tid = threadIdx.x;

    // ======== phase 0: hyper (blocks 0,1) + z transpose (all blocks) ========
    if (blockIdx.x < 2) {
        const int side = blockIdx.x;
        const float* W0; const float* b0; const float* W1; const float* b1;
        if (side == 0) { W0 = enW0; b0 = enb0; W1 = enW1; b1 = enb1; }
        else           { W0 = deW0; b0 = deb0; W1 = deW1; b1 = deb1; }
        float* mus = (float*)sm;                       // 256 floats
        float (*h1)[65] = (float(*)[65])(sm + 1024);   // 64 x 65
        __nv_bfloat16* hsH = (__nv_bfloat16*)(sm + 17664);
        __nv_bfloat16* hsL = (__nv_bfloat16*)(sm + 26880);

        mus[tid] = mu[tid];
        __syncthreads();
        for (int idx = tid; idx < 4096; idx += 256) {
            int b = idx >> 6, o = idx & 63;
            float s = b0[o];
#pragma unroll
            for (int j = 0; j < 4; j++) s += mus[b * 4 + j] * W0[o * 4 + j];
            h1[b][o] = tanhf(s);
        }
        __syncthreads();
        for (int idx = tid; idx < 4096; idx += 256) {
            int b = idx >> 6, o = idx & 63;
            float s = b1[o];
#pragma unroll
            for (int k = 0; k < 64; k++) s += h1[b][k] * W1[o * 64 + k];
            float f = tanhf(s);
            __nv_bfloat16 hi = __float2bfloat16_rn(f);
            __nv_bfloat16 lo = __float2bfloat16_rn(f - __bfloat162float(hi));
            hsH[b * 72 + o] = hi;
            hsL[b * 72 + o] = lo;
        }
        __syncthreads();
        int wid = tid >> 5, lane = tid & 31;
        if (wid < 4) {
            const int wn = wid;
            const uint32_t smbH = smem_u32(hsH), smbL = smem_u32(hsL);
            uint32_t w_[32];
            int l2 = lane & 15, rr = l2 & 7, rs = l2 >> 3;
#pragma unroll
            for (int nt = 0; nt < 2; nt++) {
                int bb = wn * 16 + nt * 8 + rr;
#pragma unroll
                for (int ks = 0; ks < 4; ks++) {
                    uint32_t o_ = (uint32_t)(bb * 144 + ks * 32 + rs * 16);
                    uint32_t th[2], tl[2];
                    ldsm_x2(th, smbH + o_);
                    ldsm_x2(tl, smbL + o_);
                    w_[nt * 8 + ks * 2 + 0] = th[0];
                    w_[nt * 8 + ks * 2 + 1] = th[1];
                    w_[16 + nt * 8 + ks * 2 + 0] = tl[0];
                    w_[16 + nt * 8 + ks * 2 + 1] = tl[1];
                }
            }
#pragma unroll
            for (int j = 0; j < 8; j++)
                g_frag[side][wn][lane][j] = make_uint4(w_[4*j], w_[4*j+1], w_[4*j+2], w_[4*j+3]);
        }
    }
    // z transpose (all blocks share)
    for (int idx = blockIdx.x * 256 + tid; idx < 2000 * 64; idx += NBLK * 256) {
        int i = idx >> 6, b = idx & 63;
        g_zT[idx] = z[b * 2000 + i];
    }
    gbar(0);

    const uint4* fragEn = &g_frag[0][0][0][0];
    const uint4* fragDe = &g_frag[1][0][0][0];

    // ======== phase 1: encoder L0  2000 -> 200, linear, 3 K-splits -> p1 ========
    run_layer(sm, fragEn, enW2, enb2, g_zT, 1, 0, 0,
              g_p1, nullptr, nullptr, 0, 0, 2000, 200, 0L, 3);
    gbar(1);
    // ======== phase 2: encoder L1  200 -> 100 (x = sum3 p1), 2 splits -> p2 ========
    run_layer(sm, fragEn, enW2, enb2, g_p1, 3, 12800, 0,
              g_p2, nullptr, nullptr, 0, 0, 200, 100, 400200L, 2);
    gbar(2);
    // ======== phase 3: encoder L2  100 -> 10 (x = tanh(sum2 p2)), 2 splits -> p1 ========
    run_layer(sm, fragEn, enW2, enb2, g_p2, 2, 6400, 1,
              g_p1, nullptr, nullptr, 0, 0, 100, 10, 420300L, 2);
    gbar(3);
    // ======== phase 4: decoder L0  10 -> 100 (x = sum2 p1), direct b3T; latent tail ========
    if (blockIdx.x == NBLK - 1) {
        for (int i = tid; i < 640; i += 256) {
            int cc = i >> 6, col = i & 63;
            out[128000 + col * 10 + cc] = g_p1[i] + g_p1[640 + i];
        }
    }
    run_layer(sm, fragDe, deW2, deb2, g_p1, 2, 640, 0,
              nullptr, g_b3T, nullptr, 0, 0, 10, 100, 0L, 1);
    gbar(4);
    // ======== phase 5: decoder L1  100 -> 200, tanh at write -> b4T ========
    run_layer(sm, fragDe, deW2, deb2, g_b3T, 1, 0, 0,
              nullptr, g_b4T, nullptr, 0, 1, 100, 200, 1100L, 1);
    gbar(5);
    // ======== phase 6: decoder L2  200 -> 2000, direct row-major to d_out ========
    run_layer(sm, fragDe, deW2, deb2, g_b4T, 1, 0, 0,
              nullptr, nullptr, out, 2000, 0, 200, 2000, 21300L, 1);
}

extern "C" void kernel_launch(void* const* d_in, const int* in_sizes, int n_in,
                              void* d_out, int out_size)
{
    const float* z    = (const float*)d_in[0];
    const float* mu   = (const float*)d_in[1];
    const float* enW0 = (const float*)d_in[2];
    const float* enb0 = (const float*)d_in[3];
    const float* enW1 = (const float*)d_in[4];
    const float* enb1 = (const float*)d_in[5];
    const float* enW2 = (const float*)d_in[6];
    const float* enb2 = (const float*)d_in[7];
    const float* deW0 = (const float*)d_in[8];
    const float* deb0 = (const float*)d_in[9];
    const float* deW1 = (const float*)d_in[10];
    const float* deb1 = (const float*)d_in[11];
    const float* deW2 = (const float*)d_in[12];
    const float* deb2 = (const float*)d_in[13];
    float* out = (float*)d_out;

    void* barc;
    cudaGetSymbolAddress(&barc, g_barc);
    cudaMemsetAsync(barc, 0, 8 * sizeof(int));

    persist<<<NBLK, 256>>>(z, mu, enW0, enb0, enW1, enb1, enW2, enb2,
                           deW0, deb0, deW1, deb1, deW2, deb2, out);
}

// round 16
// speedup vs baseline: 1.0108x; 1.0060x over previous
#include <cuda_runtime.h>
#include <cuda_bf16.h>
#include <cstdint>
#include <math.h>

#define NBLK 148
#define NTEAM (NBLK * 2)

// ================= scratch (device globals: no allocation allowed) =================
__device__ __align__(16) float g_zT [2000 * 64];
__device__ __align__(16) float g_b3T[100 * 64];
__device__ __align__(16) float g_b4T[200 * 64];
__device__ __align__(16) float g_p1[3 * 200 * 64];
__device__ __align__(16) float g_p2[2 * 200 * 64];
// h B-fragments: [side][wn][lane][8 x uint4] (words 0..15 = hi, 16..31 = lo)
__device__ __align__(16) uint4 g_frag[2][4][32][8];
__device__ int g_barc[8];

// ================= helpers =================
__device__ __forceinline__ uint32_t smem_u32(const void* p) {
    uint32_t a;
    asm("{ .reg .u64 t; cvta.to.shared.u64 t, %1; cvt.u32.u64 %0, t; }" : "=r"(a) : "l"(p));
    return a;
}
__device__ __forceinline__ void ldsm_x4(uint32_t* r, uint32_t addr) {
    asm volatile("ldmatrix.sync.aligned.m8n8.x4.shared.b16 {%0,%1,%2,%3}, [%4];"
        : "=r"(r[0]), "=r"(r[1]), "=r"(r[2]), "=r"(r[3]) : "r"(addr));
}
__device__ __forceinline__ void ldsm_x2(uint32_t* r, uint32_t addr) {
    asm volatile("ldmatrix.sync.aligned.m8n8.x2.shared.b16 {%0,%1}, [%2];"
        : "=r"(r[0]), "=r"(r[1]) : "r"(addr));
}
__device__ __forceinline__ void mma_bf16(float* d, const uint32_t* a, const uint32_t* b) {
    asm volatile("mma.sync.aligned.m16n8k16.row.col.f32.bf16.bf16.f32 "
        "{%0,%1,%2,%3}, {%4,%5,%6,%7}, {%8,%9}, {%0,%1,%2,%3};"
        : "+f"(d[0]), "+f"(d[1]), "+f"(d[2]), "+f"(d[3])
        : "r"(a[0]), "r"(a[1]), "r"(a[2]), "r"(a[3]), "r"(b[0]), "r"(b[1]));
}
__device__ __forceinline__ uint32_t prmt_hi(float a, float b) {
    uint32_t r;
    asm("prmt.b32 %0, %1, %2, 0x7632;"
        : "=r"(r) : "r"(__float_as_uint(a)), "r"(__float_as_uint(b)));
    return r;
}
__device__ __forceinline__ uint32_t pack_lo_resid(float a, float b) {
    float la = a - __uint_as_float(__float_as_uint(a) & 0xffff0000u);
    float lb = b - __uint_as_float(__float_as_uint(b) & 0xffff0000u);
    uint32_t r;
    asm("cvt.rn.bf16x2.f32 %0, %1, %2;" : "=r"(r) : "f"(lb), "f"(la));
    return r;
}

// grid-wide barrier: arrive with release, spin with acquire (thread 0 only)
__device__ __forceinline__ void gbar(int ph) {
    __syncthreads();
    if (threadIdx.x == 0) {
        __threadfence();
        atomicAdd(&g_barc[ph], 1);
        int v;
        do {
            asm volatile("ld.acquire.gpu.b32 %0, [%1];" : "=r"(v) : "l"(&g_barc[ph]) : "memory");
        } while (v < NBLK);
    }
    __syncthreads();
}

// ================= smem layout =================
// layers: wt[team] 9216 each @0, b2s float[2][3][16] @18432 (384)
// phase0 overlay: mus @0 (1024), h1 @1024 (16640), hsH @17664 (9216), hsL @26880 (9216)
#define SM_BYTES 36608

// ================= fused hyper-FC layer (one phase) =================
// Team (128 thr) owns task = (channel, K-split); static stride NTEAM.
// Per 16-row tile: D[j,b] = Wrows @ h^T (3-term bf16 split, fp32 acc);
//   acc[b] += (D[j,b] + b2[j]) * x'[j,b]   (x'[ni] = 1 folds the layer bias).
// x read from xsrc; if np>1 sums np partial arrays (stride pstride), opt tanh.
__device__ __noinline__ void run_layer(
    char* sm, const uint4* hfrag,
    const float* __restrict__ W2, const float* __restrict__ b2,
    const float* __restrict__ xsrc, int np, int pstride, int xtanh,
    float* __restrict__ part_out, float* __restrict__ outT,
    float* __restrict__ outR, int ostride, int otanh,
    int ni, int no, long off, int nsplit)
{
    const int tid = threadIdx.x, lane = tid & 31, wid = tid >> 5;
    const int team = wid >> 2, wn = wid & 3, tt = tid & 127;
    char* wt = sm + team * 9216;                       // 2 stages x {hi 2304, lo 2304}
    float* b2s = (float*)(sm + 18432) + team * 48;     // [3 slots][16]
    const uint32_t wtb = smem_u32(wt);
    const int barid = 1 + team;
    const int sr = tt >> 3, sq = tt & 7;

    // ---- B fragments: 8 coalesced LDG.128 ----
    uint32_t bh[2][4][2], bl[2][4][2];
    {
        const uint4* fp = hfrag + (wn * 32 + lane) * 8;
        uint32_t w_[32];
#pragma unroll
        for (int j = 0; j < 8; j++) {
            uint4 v = fp[j];
            w_[4*j] = v.x; w_[4*j+1] = v.y; w_[4*j+2] = v.z; w_[4*j+3] = v.w;
        }
#pragma unroll
        for (int nt = 0; nt < 2; nt++)
#pragma unroll
        for (int ks = 0; ks < 4; ks++)
#pragma unroll
        for (int r = 0; r < 2; r++) {
            bh[nt][ks][r] = w_[nt * 8 + ks * 2 + r];
            bl[nt][ks][r] = w_[16 + nt * 8 + ks * 2 + r];
        }
    }

    const int K1 = ni + 1;
    const int ilen = (K1 + nsplit - 1) / nsplit;
    const int ntasks = no * nsplit;

    for (int task = blockIdx.x * 2 + team; task < ntasks; task += NTEAM) {
        const int cc = task / nsplit, split = task % nsplit;
        const int ibeg = split * ilen;
        const int iend = min(ibeg + ilen, K1);
        const int ntiles = (iend - ibeg + 15) >> 4;
        const long wbase = off + (long)cc * ni;
        const long brow  = off + (long)ni * no + cc;

        float4 pwa[3], pwb[3]; float pb2[3];
        auto ldg_tile = [&](int t) {
            int s = t % 3;
            int gi = ibeg + t * 16 + sr;
            bool valid = gi < iend;
            long row = (gi < ni) ? (wbase + gi) : brow;
            const float4 f40 = make_float4(0.f, 0.f, 0.f, 0.f);
            pwa[s] = valid ? *(const float4*)(W2 + row * 64 + sq * 8)     : f40;
            pwb[s] = valid ? *(const float4*)(W2 + row * 64 + sq * 8 + 4) : f40;
            pb2[s] = (valid && sq == 0) ? b2[row] : 0.f;
        };
        auto sts_tile = [&](int t) {
            int s = t % 3, sbuf = t & 1;
            char* ph = wt + sbuf * 4608 + sr * 144 + sq * 16;
            uint4 H, L;
            H.x = prmt_hi(pwa[s].x, pwa[s].y); H.y = prmt_hi(pwa[s].z, pwa[s].w);
            H.z = prmt_hi(pwb[s].x, pwb[s].y); H.w = prmt_hi(pwb[s].z, pwb[s].w);
            L.x = pack_lo_resid(pwa[s].x, pwa[s].y); L.y = pack_lo_resid(pwa[s].z, pwa[s].w);
            L.z = pack_lo_resid(pwb[s].x, pwb[s].y); L.w = pack_lo_resid(pwb[s].z, pwb[s].w);
            *(uint4*)ph = H;
            *(uint4*)(ph + 2304) = L;
            if (sq == 0) b2s[sbuf * 16 + sr] = pb2[s];
        };

        ldg_tile(0);
        if (ntiles > 1) ldg_tile(1);
        if (ntiles > 2) ldg_tile(2);
        asm volatile("bar.sync %0, 128;" :: "r"(barid) : "memory");  // prev task done with smem
        sts_tile(0);

        float acc[4] = {0.f, 0.f, 0.f, 0.f};
        const float2 z2 = make_float2(0.f, 0.f);

        for (int mt = 0; mt < ntiles; ++mt) {
            if (mt + 3 < ntiles) ldg_tile(mt + 3);
            asm volatile("bar.sync %0, 128;" :: "r"(barid) : "memory");

            // ---- x loads (inline partial-sum + opt tanh) ----
            const int g0 = ibeg + mt * 16 + (lane >> 2);
            const int g1 = g0 + 8;
            const bool v0 = g0 < iend, v1 = g1 < iend;
            float2 x0[2], x1[2];
#pragma unroll
            for (int nt = 0; nt < 2; nt++) {
                int col = wn * 16 + nt * 8 + (lane & 3) * 2;
#pragma unroll
                for (int half = 0; half < 2; half++) {
                    int g = half ? g1 : g0;
                    bool v = half ? v1 : v0;
                    float2 xv = z2;
                    if (v) {
                        if (g == ni) xv = make_float2(1.f, 1.f);
                        else {
                            const float* p = xsrc + (long)g * 64 + col;
                            xv = *(const float2*)p;
                            if (np > 1) {
                                float2 a = *(const float2*)(p + pstride);
                                xv.x += a.x; xv.y += a.y;
                                if (np > 2) {
                                    float2 b = *(const float2*)(p + 2 * pstride);
                                    xv.x += b.x; xv.y += b.y;
                                }
                            }
                            if (xtanh) { xv.x = tanhf(xv.x); xv.y = tanhf(xv.y); }
                        }
                    }
                    if (half) x1[nt] = xv; else x0[nt] = xv;
                }
            }

            // ---- A fragments via ldmatrix ----
            const int buf = mt & 1;
            uint32_t aH[4][4], aL[4][4];
            {
                int lrow = (lane & 7) + ((lane >> 3) & 1) * 8;
                int kh = lane >> 4;
                uint32_t base = wtb + buf * 4608 + (uint32_t)(lrow * 144 + kh * 16);
#pragma unroll
                for (int ks = 0; ks < 4; ks++) {
                    ldsm_x4(aH[ks], base + ks * 32);
                    ldsm_x4(aL[ks], base + 2304 + ks * 32);
                }
            }

            // ---- MMA (3-term split) ----
            float d[2][4] = {{0.f,0.f,0.f,0.f},{0.f,0.f,0.f,0.f}};
#pragma unroll
            for (int ks = 0; ks < 4; ks++) {
#pragma unroll
                for (int nt = 0; nt < 2; nt++) {
                    mma_bf16(d[nt], aH[ks], bh[nt][ks]);
                    mma_bf16(d[nt], aH[ks], bl[nt][ks]);
                    mma_bf16(d[nt], aL[ks], bh[nt][ks]);
                }
            }

            // ---- fold bias + x ----
            const float bb0 = b2s[buf * 16 + (lane >> 2)];
            const float bb1 = b2s[buf * 16 + (lane >> 2) + 8];
#pragma unroll
            for (int nt = 0; nt < 2; nt++) {
                acc[nt * 2 + 0] += (d[nt][0] + bb0) * x0[nt].x + (d[nt][2] + bb1) * x1[nt].x;
                acc[nt * 2 + 1] += (d[nt][1] + bb0) * x0[nt].y + (d[nt][3] + bb1) * x1[nt].y;
            }

            if (mt + 1 < ntiles) sts_tile(mt + 1);
        }

        // ---- reduce over j-groups (lane bits 2..4) and write ----
#pragma unroll
        for (int e = 0; e < 4; e++) {
            acc[e] += __shfl_xor_sync(0xffffffffu, acc[e], 4);
            acc[e] += __shfl_xor_sync(0xffffffffu, acc[e], 8);
            acc[e] += __shfl_xor_sync(0xffffffffu, acc[e], 16);
        }
        if (lane < 4) {
#pragma unroll
            for (int nt = 0; nt < 2; nt++)
#pragma unroll
            for (int e2 = 0; e2 < 2; e2++) {
                int col = wn * 16 + nt * 8 + lane * 2 + e2;
                float v = acc[nt * 2 + e2];
                if (part_out) {
                    part_out[(long)split * (no * 64) + (long)cc * 64 + col] = v;
                } else {
                    if (otanh) v = tanhf(v);
                    if (outT) outT[(long)cc * 64 + col] = v;
                    if (outR) outR[(long)col * ostride + cc] = v;
                }
            }
        }
    }
}

// ================= the persistent kernel =================
__global__ void __launch_bounds__(256, 1) persist(
    const float* __restrict__ z, const float* __restrict__ mu,
    const float* __restrict__ enW0, const float* __restrict__ enb0,
    const float* __restrict__ enW1, const float* __restrict__ enb1,
    const float* __restrict__ enW2, const float* __restrict__ enb2,
    const float* __restrict__ deW0, const float* __restrict__ deb0,
    const float* __restrict__ deW1, const float* __restrict__ deb1,
    const float* __restrict__ deW2, const float* __restrict__ deb2,
    float* __restrict__ out)
{
    __shared__ __align__(16) char sm[SM_BYTES];
    const int tid = threadIdx.x;

    // ======== phase 0: hyper (blocks 0,1) + z transpose (all blocks) ========
    if (blockIdx.x < 2) {
        const int side = blockIdx.x;
        const float* W0; const float* b0; const float* W1; const float* b1;
        if (side == 0) { W0 = enW0; b0 = enb0; W1 = enW1; b1 = enb1; }
        else           { W0 = deW0; b0 = deb0; W1 = deW1; b1 = deb1; }
        float* mus = (float*)sm;                       // 256 floats
        float (*h1)[65] = (float(*)[65])(sm + 1024);   // 64 x 65
        __nv_bfloat16* hsH = (__nv_bfloat16*)(sm + 17664);
        __nv_bfloat16* hsL = (__nv_bfloat16*)(sm + 26880);

        mus[tid] = mu[tid];
        __syncthreads();
        for (int idx = tid; idx < 4096; idx += 256) {
            int b = idx >> 6, o = idx & 63;
            float s = b0[o];
#pragma unroll
            for (int j = 0; j < 4; j++) s += mus[b * 4 + j] * W0[o * 4 + j];
            h1[b][o] = tanhf(s);
        }
        __syncthreads();
        for (int idx = tid; idx < 4096; idx += 256) {
            int b = idx >> 6, o = idx & 63;
            float s = b1[o];
#pragma unroll
            for (int k = 0; k < 64; k++) s += h1[b][k] * W1[o * 64 + k];
            float f = tanhf(s);
            __nv_bfloat16 hi = __float2bfloat16_rn(f);
            __nv_bfloat16 lo = __float2bfloat16_rn(f - __bfloat162float(hi));
            hsH[b * 72 + o] = hi;
            hsL[b * 72 + o] = lo;
        }
        __syncthreads();
        int wid = tid >> 5, lane = tid & 31;
        if (wid < 4) {
            const int wn = wid;
            const uint32_t smbH = smem_u32(hsH), smbL = smem_u32(hsL);
            uint32_t w_[32];
            int l2 = lane & 15, rr = l2 & 7, rs = l2 >> 3;
#pragma unroll
            for (int nt = 0; nt < 2; nt++) {
                int bb = wn * 16 + nt * 8 + rr;
#pragma unroll
                for (int ks = 0; ks < 4; ks++) {
                    uint32_t o_ = (uint32_t)(bb * 144 + ks * 32 + rs * 16);
                    uint32_t th[2], tl[2];
                    ldsm_x2(th, smbH + o_);
                    ldsm_x2(tl, smbL + o_);
                    w_[nt * 8 + ks * 2 + 0] = th[0];
                    w_[nt * 8 + ks * 2 + 1] = th[1];
                    w_[16 + nt * 8 + ks * 2 + 0] = tl[0];
                    w_[16 + nt * 8 + ks * 2 + 1] = tl[1];
                }
            }
#pragma unroll
            for (int j = 0; j < 8; j++)
                g_frag[side][wn][lane][j] = make_uint4(w_[4*j], w_[4*j+1], w_[4*j+2], w_[4*j+3]);
        }
    }
    // z transpose (all blocks share)
    for (int idx = blockIdx.x * 256 + tid; idx < 2000 * 64; idx += NBLK * 256) {
        int i = idx >> 6, b = idx & 63;
        g_zT[idx] = z[b * 2000 + i];
    }
    gbar(0);

    const uint4* fragEn = &g_frag[0][0][0][0];
    const uint4* fragDe = &g_frag[1][0][0][0];

    // ======== phase 1: encoder L0  2000 -> 200, linear, 3 K-splits -> p1 ========
    run_layer(sm, fragEn, enW2, enb2, g_zT, 1, 0, 0,
              g_p1, nullptr, nullptr, 0, 0, 2000, 200, 0L, 3);
    gbar(1);
    // ======== phase 2: encoder L1  200 -> 100 (x = sum3 p1), 2 splits -> p2 ========
    run_layer(sm, fragEn, enW2, enb2, g_p1, 3, 12800, 0,
              g_p2, nullptr, nullptr, 0, 0, 200, 100, 400200L, 2);
    gbar(2);
    // ======== phase 3: encoder L2  100 -> 10 (x = tanh(sum2 p2)), 2 splits -> p1 ========
    run_layer(sm, fragEn, enW2, enb2, g_p2, 2, 6400, 1,
              g_p1, nullptr, nullptr, 0, 0, 100, 10, 420300L, 2);
    gbar(3);
    // ======== phase 4: decoder L0  10 -> 100 (x = sum2 p1), direct b3T; latent tail ========
    if (blockIdx.x == NBLK - 1) {
        for (int i = tid; i < 640; i += 256) {
            int cc = i >> 6, col = i & 63;
            out[128000 + col * 10 + cc] = g_p1[i] + g_p1[640 + i];
        }
    }
    run_layer(sm, fragDe, deW2, deb2, g_p1, 2, 640, 0,
              nullptr, g_b3T, nullptr, 0, 0, 10, 100, 0L, 1);
    gbar(4);
    // ======== phase 5: decoder L1  100 -> 200, tanh at write -> b4T ========
    run_layer(sm, fragDe, deW2, deb2, g_b3T, 1, 0, 0,
              nullptr, g_b4T, nullptr, 0, 1, 100, 200, 1100L, 1);
    gbar(5);
    // ======== phase 6: decoder L2  200 -> 2000, direct row-major to d_out ========
    run_layer(sm, fragDe, deW2, deb2, g_b4T, 1, 0, 0,
              nullptr, nullptr, out, 2000, 0, 200, 2000, 21300L, 1);
}

extern "C" void kernel_launch(void* const* d_in, const int* in_sizes, int n_in,
                              void* d_out, int out_size)
{
    const float* z    = (const float*)d_in[0];
    const float* mu   = (const float*)d_in[1];
    const float* enW0 = (const float*)d_in[2];
    const float* enb0 = (const float*)d_in[3];
    const float* enW1 = (const float*)d_in[4];
    const float* enb1 = (const float*)d_in[5];
    const float* enW2 = (const float*)d_in[6];
    const float* enb2 = (const float*)d_in[7];
    const float* deW0 = (const float*)d_in[8];
    const float* deb0 = (const float*)d_in[9];
    const float* deW1 = (const float*)d_in[10];
    const float* deb1 = (const float*)d_in[11];
    const float* deW2 = (const float*)d_in[12];
    const float* deb2 = (const float*)d_in[13];
    float* out = (float*)d_out;

    void* barc;
    cudaGetSymbolAddress(&barc, g_barc);
    cudaMemsetAsync(barc, 0, 8 * sizeof(int));

    persist<<<NBLK, 256>>>(z, mu, enW0, enb0, enW1, enb1, enW2, enb2,
                           deW0, deb0, deW1, deb1, deW2, deb2, out);
}